// round 1
// baseline (speedup 1.0000x reference)
#include <cuda_runtime.h>

#define SEQ   20
#define BATCH 16384
#define INP   2
#define HID   256
#define EMB   64
#define TLEN  30
#define NG    1024   /* 4*HID */

#define KENC  320    /* 256 + 64 */
#define KDEC  264    /* 256 + 2, padded to multiple of 8 */

// ---------------- device scratch (no allocations allowed) ----------------
__device__ float g_Wp_enc[KENC * NG];      // packed: Wp[k][n], n = j*4+g
__device__ float g_Wp_dec[KDEC * NG];
__device__ float g_bias_enc[NG];           // permuted bias
__device__ float g_bias_dec[NG];
__device__ float g_h[2][BATCH * HID];      // ping-pong hidden state
__device__ float g_c[BATCH * HID];         // cell state (updated in place)
__device__ float g_xemb[SEQ * BATCH * EMB];

// ---------------- helpers ----------------
__device__ __forceinline__ float fsigmoid(float x) {
    return 1.0f / (1.0f + __expf(-x));
}
__device__ __forceinline__ float ftanh(float x) {
    // tanh(x) = 2*sigmoid(2x) - 1   (error ~few ulp with __expf)
    return 2.0f / (1.0f + __expf(-2.0f * x)) - 1.0f;
}

// ---------------- weight packing ----------------
__global__ void pack_enc_kernel(const float* __restrict__ W_ih,
                                const float* __restrict__ W_hh,
                                const float* __restrict__ b) {
    int idx = blockIdx.x * blockDim.x + threadIdx.x;
    if (idx < KENC * NG) {
        int k = idx / NG, n = idx % NG;
        int j = n >> 2, g = n & 3;
        int row = g * HID + j;
        g_Wp_enc[idx] = (k < HID) ? W_hh[row * HID + k]
                                  : W_ih[row * EMB + (k - HID)];
    }
    if (idx < NG) {
        int j = idx >> 2, g = idx & 3;
        g_bias_enc[idx] = b[g * HID + j];
    }
}

__global__ void pack_dec_kernel(const float* __restrict__ W_ih,
                                const float* __restrict__ W_hh,
                                const float* __restrict__ b) {
    int idx = blockIdx.x * blockDim.x + threadIdx.x;
    if (idx < KDEC * NG) {
        int k = idx / NG, n = idx % NG;
        int j = n >> 2, g = n & 3;
        int row = g * HID + j;
        float v;
        if (k < HID)            v = W_hh[row * HID + k];
        else if (k - HID < INP) v = W_ih[row * INP + (k - HID)];
        else                    v = 0.0f;
        g_Wp_dec[idx] = v;
    }
    if (idx < NG) {
        int j = idx >> 2, g = idx & 3;
        g_bias_dec[idx] = b[g * HID + j];
    }
}

// ---------------- init (h0 = 0, c0 = 0) ----------------
__global__ void init_state_kernel() {
    int idx = blockIdx.x * blockDim.x + threadIdx.x;
    if (idx < BATCH * HID) {
        g_h[0][idx] = 0.0f;
        g_c[idx]    = 0.0f;
    }
}

// ---------------- embedding: x_emb = x @ W_emb^T + b_emb ----------------
__global__ void embed_kernel(const float* __restrict__ x,
                             const float* __restrict__ W_emb,
                             const float* __restrict__ b_emb) {
    int idx = blockIdx.x * blockDim.x + threadIdx.x;
    if (idx >= SEQ * BATCH * EMB) return;
    int e  = idx & (EMB - 1);
    int tb = idx >> 6;             // t*BATCH + b
    float x0 = x[tb * 2 + 0];
    float x1 = x[tb * 2 + 1];
    g_xemb[idx] = b_emb[e] + x0 * W_emb[e * 2 + 0] + x1 * W_emb[e * 2 + 1];
}

// ---------------- fused LSTM step: GEMM + cell update ----------------
// C[B,1024] = [h | x] @ Wp  (Wp is k-major packed), then gate math.
// Tile: 128 (batch) x 128 (cols = 32 j * 4 gates), BK=8, 256 threads, 8x8 micro.
template <int KTOT, int XDIM, bool ENC>
__global__ void __launch_bounds__(256, 2)
lstm_step_kernel(const float* __restrict__ xsrc_ext, int t, int pp) {
    const float* __restrict__ Wp   = ENC ? g_Wp_enc  : g_Wp_dec;
    const float* __restrict__ bp   = ENC ? g_bias_enc : g_bias_dec;
    const float* __restrict__ h_in = g_h[pp];
    float* __restrict__       h_out = g_h[pp ^ 1];
    const float* __restrict__ xsrc =
        ENC ? (g_xemb + (size_t)t * BATCH * EMB) : xsrc_ext;

    __shared__ float As[8][132];   // padded: kills store bank conflicts
    __shared__ float Bs[8][128];

    const int tid = threadIdx.x;
    const int m0  = blockIdx.x * 128;
    const int n0  = blockIdx.y * 128;

    float acc[8][8];
#pragma unroll
    for (int i = 0; i < 8; i++)
#pragma unroll
        for (int j = 0; j < 8; j++) acc[i][j] = 0.0f;

    const int arow = tid >> 1;          // 0..127
    const int acol = (tid & 1) * 4;     // 0 or 4
    const int brow = tid >> 5;          // 0..7
    const int bcol = (tid & 31) * 4;    // 0..124
    const int trow = (tid >> 4) * 8;    // 0..120
    const int tcol = (tid & 15) * 8;    // 0..120
    const int ab   = m0 + arow;

    for (int k0 = 0; k0 < KTOT; k0 += 8) {
        // ---- load A tile (h | x | 0) ----
        int kg = k0 + acol;
        float4 av;
        if (ENC) {
            const float* src = (kg < HID)
                ? &h_in[(size_t)ab * HID + kg]
                : &xsrc[(size_t)ab * XDIM + (kg - HID)];
            av = *(const float4*)src;
        } else {
            if (kg < HID) {
                av = *(const float4*)&h_in[(size_t)ab * HID + kg];
            } else {
                float tv[4];
#pragma unroll
                for (int q = 0; q < 4; q++) {
                    int kk = kg + q - HID;
                    tv[q] = (kk < XDIM) ? xsrc[(size_t)ab * XDIM + kk] : 0.0f;
                }
                av = make_float4(tv[0], tv[1], tv[2], tv[3]);
            }
        }
        As[acol + 0][arow] = av.x;
        As[acol + 1][arow] = av.y;
        As[acol + 2][arow] = av.z;
        As[acol + 3][arow] = av.w;

        // ---- load B tile (packed weights, coalesced) ----
        float4 bv = *(const float4*)&Wp[(size_t)(k0 + brow) * NG + n0 + bcol];
        *(float4*)&Bs[brow][bcol] = bv;

        __syncthreads();

#pragma unroll
        for (int k = 0; k < 8; k++) {
            float4 a0 = *(const float4*)&As[k][trow];
            float4 a1 = *(const float4*)&As[k][trow + 4];
            float4 b0 = *(const float4*)&Bs[k][tcol];
            float4 b1 = *(const float4*)&Bs[k][tcol + 4];
            float a[8] = {a0.x, a0.y, a0.z, a0.w, a1.x, a1.y, a1.z, a1.w};
            float bb[8] = {b0.x, b0.y, b0.z, b0.w, b1.x, b1.y, b1.z, b1.w};
#pragma unroll
            for (int i = 0; i < 8; i++)
#pragma unroll
                for (int j = 0; j < 8; j++)
                    acc[i][j] = fmaf(a[i], bb[j], acc[i][j]);
        }
        __syncthreads();
    }

    // ---- epilogue: cell update. Each thread owns 8 rows x 2 hidden units. ----
#pragma unroll
    for (int i = 0; i < 8; i++) {
        int b = m0 + trow + i;
#pragma unroll
        for (int jj = 0; jj < 2; jj++) {
            int nc = n0 + tcol + jj * 4;
            float gi = acc[i][jj * 4 + 0] + bp[nc + 0];
            float gf = acc[i][jj * 4 + 1] + bp[nc + 1];
            float gg = acc[i][jj * 4 + 2] + bp[nc + 2];
            float go = acc[i][jj * 4 + 3] + bp[nc + 3];
            int j = nc >> 2;
            size_t sidx = (size_t)b * HID + j;
            float cold = g_c[sidx];
            float cn = fsigmoid(gf) * cold + fsigmoid(gi) * ftanh(gg);
            g_c[sidx]   = cn;
            h_out[sidx] = fsigmoid(go) * ftanh(cn);
        }
    }
}

// ---------------- decoder output: out = h @ W_out^T + b_out (one warp / row) ----
__global__ void out_kernel(int pp, const float* __restrict__ W_out,
                           const float* __restrict__ b_out,
                           float* __restrict__ out) {
    int gwarp = (blockIdx.x * blockDim.x + threadIdx.x) >> 5;
    int lane  = threadIdx.x & 31;
    if (gwarp >= BATCH) return;
    const float* hr = g_h[pp] + (size_t)gwarp * HID;
    float s0 = 0.0f, s1 = 0.0f;
#pragma unroll
    for (int k = lane; k < HID; k += 32) {
        float hv = hr[k];
        s0 += hv * W_out[k];
        s1 += hv * W_out[HID + k];
    }
#pragma unroll
    for (int off = 16; off > 0; off >>= 1) {
        s0 += __shfl_down_sync(0xffffffffu, s0, off);
        s1 += __shfl_down_sync(0xffffffffu, s1, off);
    }
    if (lane == 0) {
        out[gwarp * 2 + 0] = s0 + b_out[0];
        out[gwarp * 2 + 1] = s1 + b_out[1];
    }
}

// ---------------- launch ----------------
extern "C" void kernel_launch(void* const* d_in, const int* in_sizes, int n_in,
                              void* d_out, int out_size) {
    const float* x        = (const float*)d_in[0];
    const float* W_emb    = (const float*)d_in[1];
    const float* b_emb    = (const float*)d_in[2];
    const float* W_ih_enc = (const float*)d_in[3];
    const float* W_hh_enc = (const float*)d_in[4];
    const float* b_enc    = (const float*)d_in[5];
    const float* W_ih_dec = (const float*)d_in[6];
    const float* W_hh_dec = (const float*)d_in[7];
    const float* b_dec    = (const float*)d_in[8];
    const float* W_out    = (const float*)d_in[9];
    const float* b_out    = (const float*)d_in[10];
    float* out = (float*)d_out;

    pack_enc_kernel<<<(KENC * NG + 255) / 256, 256>>>(W_ih_enc, W_hh_enc, b_enc);
    pack_dec_kernel<<<(KDEC * NG + 255) / 256, 256>>>(W_ih_dec, W_hh_dec, b_dec);
    init_state_kernel<<<(BATCH * HID + 255) / 256, 256>>>();
    embed_kernel<<<(SEQ * BATCH * EMB + 255) / 256, 256>>>(x, W_emb, b_emb);

    dim3 grid(BATCH / 128, NG / 128);
    int pp = 0;

    // encoder
    for (int t = 0; t < SEQ; t++) {
        lstm_step_kernel<KENC, EMB, true><<<grid, 256>>>(nullptr, t, pp);
        pp ^= 1;
    }

    // autoregressive decoder
    for (int t = 0; t < TLEN; t++) {
        const float* xs = (t == 0) ? (x + (size_t)(SEQ - 1) * BATCH * INP)
                                   : (out + (size_t)(t - 1) * BATCH * INP);
        lstm_step_kernel<KDEC, INP, false><<<grid, 256>>>(xs, 0, pp);
        pp ^= 1;
        out_kernel<<<(BATCH * 32) / 256, 256>>>(pp, W_out, b_out,
                                                out + (size_t)t * BATCH * INP);
    }
}

// round 3
// speedup vs baseline: 1.0132x; 1.0132x over previous
#include <cuda_runtime.h>
#include <cuda_bf16.h>
#include <cstdint>

#define SEQ   20
#define BATCH 16384
#define INP   2
#define HID   256
#define EMB   64
#define TLEN  30
#define NG    1024          /* 4*HID */
#define KP    320           /* per-part K: 256 h + 64 x */
#define KTOT  960           /* 3 parts: [Ah|Ah|Al] x [Wh|Wl|Wh] */
#define KC    64            /* K per chunk (128B bf16 rows, SW128) */
#define NCH   15            /* KTOT / KC */

#define M_CTA  256
#define N_CTA  128
#define NSTAGE 3
#define A_BYTES (M_CTA * KC * 2)              /* 32KB */
#define B_BYTES (N_CTA * KC * 2)              /* 16KB */
#define STAGE_BYTES (A_BYTES + B_BYTES)       /* 48KB */
#define SMEM_DYN_TOTAL (NSTAGE * STAGE_BYTES) /* 144KB */

// ---------------- device scratch ----------------
__device__ __nv_bfloat16 g_Wt_enc[NG * KTOT];   // [n][k] row-major
__device__ __nv_bfloat16 g_Wt_dec[NG * KTOT];
__device__ float g_bias_enc[NG];
__device__ float g_bias_dec[NG];
__device__ __nv_bfloat16 g_Hh[2][BATCH * HID];
__device__ __nv_bfloat16 g_Hl[2][BATCH * HID];
__device__ float g_c[BATCH * HID];
__device__ __nv_bfloat16 g_Xh_enc[SEQ * BATCH * EMB];
__device__ __nv_bfloat16 g_Xl_enc[SEQ * BATCH * EMB];
__device__ __nv_bfloat16 g_Xdh[BATCH * EMB];
__device__ __nv_bfloat16 g_Xdl[BATCH * EMB];

// ---------------- helpers ----------------
__device__ __forceinline__ uint32_t smem_to_u32(const void* p) {
    uint32_t a;
    asm("{ .reg .u64 t; cvta.to.shared.u64 t, %1; cvt.u32.u64 %0, t; }"
        : "=r"(a) : "l"(p));
    return a;
}
#define SWZ(o) ((o) ^ (((o) >> 3) & 0x70))

#define CP_ASYNC16(s, g) \
    asm volatile("cp.async.cg.shared.global [%0], [%1], 16;" \
                 :: "r"((uint32_t)(s)), "l"(g) : "memory")
#define CP_COMMIT() asm volatile("cp.async.commit_group;" ::: "memory")
#define CP_WAIT2()  asm volatile("cp.async.wait_group 2;" ::: "memory")

__device__ __forceinline__ void ldm_x4(uint32_t& r0, uint32_t& r1,
                                       uint32_t& r2, uint32_t& r3, uint32_t a) {
    asm volatile("ldmatrix.sync.aligned.m8n8.x4.shared.b16 {%0,%1,%2,%3}, [%4];"
                 : "=r"(r0), "=r"(r1), "=r"(r2), "=r"(r3) : "r"(a));
}
__device__ __forceinline__ void mma_bf16(float* c, const uint32_t* a,
                                         uint32_t b0, uint32_t b1) {
    asm volatile(
        "mma.sync.aligned.m16n8k16.row.col.f32.bf16.bf16.f32 "
        "{%0,%1,%2,%3}, {%4,%5,%6,%7}, {%8,%9}, {%0,%1,%2,%3};"
        : "+f"(c[0]), "+f"(c[1]), "+f"(c[2]), "+f"(c[3])
        : "r"(a[0]), "r"(a[1]), "r"(a[2]), "r"(a[3]), "r"(b0), "r"(b1));
}

__device__ __forceinline__ float fsigmoid(float x) { return 1.0f / (1.0f + __expf(-x)); }
__device__ __forceinline__ float ftanh(float x)    { return 2.0f / (1.0f + __expf(-2.0f * x)) - 1.0f; }

// ---------------- pack: W' = [Wh | Wl | Wh], n-major, bf16 split ----------------
template <bool ENC>
__global__ void pack_kernel(const float* __restrict__ W_ih,
                            const float* __restrict__ W_hh,
                            const float* __restrict__ b) {
    int idx = blockIdx.x * blockDim.x + threadIdx.x;
    if (idx < NG * KTOT) {
        int n = idx / KTOT, kk = idx % KTOT;
        int p = kk / KP, k = kk % KP;
        int j = n >> 2, g = n & 3;
        int row = g * HID + j;
        float v;
        if (k < HID) v = W_hh[row * HID + k];
        else {
            int kx = k - HID;
            if (ENC) v = W_ih[row * EMB + kx];
            else     v = (kx < INP) ? W_ih[row * INP + kx] : 0.0f;
        }
        __nv_bfloat16 hi = __float2bfloat16(v);
        __nv_bfloat16 ov = (p == 1) ? __float2bfloat16(v - __bfloat162float(hi)) : hi;
        (ENC ? g_Wt_enc : g_Wt_dec)[idx] = ov;
    }
    if (idx < NG) {
        int j = idx >> 2, g = idx & 3;
        (ENC ? g_bias_enc : g_bias_dec)[idx] = b[g * HID + j];
    }
}

__global__ void init_state_kernel() {
    int idx = blockIdx.x * blockDim.x + threadIdx.x;
    if (idx < BATCH * HID) {
        g_Hh[0][idx] = __float2bfloat16(0.0f);
        g_Hl[0][idx] = __float2bfloat16(0.0f);
        g_c[idx]     = 0.0f;
    }
}

__global__ void embed_kernel(const float* __restrict__ x,
                             const float* __restrict__ W_emb,
                             const float* __restrict__ b_emb) {
    int idx = blockIdx.x * blockDim.x + threadIdx.x;
    if (idx >= SEQ * BATCH * EMB) return;
    int e  = idx & (EMB - 1);
    int tb = idx >> 6;
    float x0 = x[tb * 2 + 0];
    float x1 = x[tb * 2 + 1];
    float v = b_emb[e] + x0 * W_emb[e * 2 + 0] + x1 * W_emb[e * 2 + 1];
    __nv_bfloat16 hi = __float2bfloat16(v);
    g_Xh_enc[idx] = hi;
    g_Xl_enc[idx] = __float2bfloat16(v - __bfloat162float(hi));
}

__global__ void dec_prep_kernel(const float* __restrict__ x) {
    int idx = blockIdx.x * blockDim.x + threadIdx.x;
    if (idx >= BATCH * EMB) return;
    int b = idx >> 6, col = idx & 63;
    float v = (col < INP) ? x[(size_t)(SEQ - 1) * BATCH * INP + b * INP + col] : 0.0f;
    __nv_bfloat16 hi = __float2bfloat16(v);
    g_Xdh[idx] = hi;
    g_Xdl[idx] = __float2bfloat16(v - __bfloat162float(hi));
}

// ---------------- fused HMMA LSTM step ----------------
// C[B,1024] = A'[B,960] * W'^T, fused gate/cell update.
// CTA 256(M)x128(N), 512 thr, 16 warps (4m x 4n), warp tile 64x32.
template <bool ENC>
__global__ void __launch_bounds__(512, 1)
lstm_step_kernel(int t, int ppi) {
    extern __shared__ __align__(1024) char smem_raw[];
    const uint32_t sb = smem_to_u32(smem_raw);
    const int tid  = threadIdx.x;
    const int warp = tid >> 5, lane = tid & 31;
    const int wm = warp >> 2, wn = warp & 3;
    const int m0 = blockIdx.x * M_CTA, n0 = blockIdx.y * N_CTA;

    const __nv_bfloat16* __restrict__ Wt = ENC ? g_Wt_enc : g_Wt_dec;
    const float* __restrict__ bias       = ENC ? g_bias_enc : g_bias_dec;
    const __nv_bfloat16* __restrict__ hh = g_Hh[ppi];
    const __nv_bfloat16* __restrict__ hl = g_Hl[ppi];
    __nv_bfloat16* __restrict__ hho      = g_Hh[ppi ^ 1];
    __nv_bfloat16* __restrict__ hlo      = g_Hl[ppi ^ 1];
    const __nv_bfloat16* __restrict__ xh =
        ENC ? (g_Xh_enc + (size_t)t * BATCH * EMB) : g_Xdh;
    const __nv_bfloat16* __restrict__ xl =
        ENC ? (g_Xl_enc + (size_t)t * BATCH * EMB) : g_Xdl;

    // ---- chunk loader: A (256x64) + W (128x64), SW128 swizzled ----
    auto load_chunk = [&](int ck, int st) {
        const __nv_bfloat16* ab; int astr, coff;
        if (ck == 4 || ck == 9) { ab = xh; astr = EMB; coff = 0; }
        else if (ck == 14)      { ab = xl; astr = EMB; coff = 0; }
        else if (ck < 4)        { ab = hh; astr = HID; coff = ck * KC; }
        else if (ck < 9)        { ab = hh; astr = HID; coff = (ck - 5) * KC; }
        else                    { ab = hl; astr = HID; coff = (ck - 10) * KC; }
        const uint32_t sA = sb + st * STAGE_BYTES;
        const uint32_t sB = sA + A_BYTES;
        // A: 256 rows x 8 segs(16B) = 2048 transfers, 4/thread
        {
            const int r = tid >> 1;
            const __nv_bfloat16* g = ab + (size_t)(m0 + r) * astr + coff;
#pragma unroll
            for (int i = 0; i < 4; i++) {
                const int seg = ((tid & 1) << 2) + i;
                CP_ASYNC16(sA + SWZ(r * 128 + seg * 16), g + seg * 8);
            }
        }
        // B: 128 rows x 8 segs = 1024 transfers, 2/thread
        {
            const int r = tid >> 2;
            const __nv_bfloat16* g = Wt + (size_t)(n0 + r) * KTOT + ck * KC;
#pragma unroll
            for (int i = 0; i < 2; i++) {
                const int seg = ((tid & 3) << 1) + i;
                CP_ASYNC16(sB + SWZ(r * 128 + seg * 16), g + seg * 8);
            }
        }
    };

    float acc[4][4][4];
#pragma unroll
    for (int a = 0; a < 4; a++)
#pragma unroll
        for (int b = 0; b < 4; b++)
#pragma unroll
            for (int c = 0; c < 4; c++) acc[a][b][c] = 0.0f;

    load_chunk(0, 0); CP_COMMIT();
    load_chunk(1, 1); CP_COMMIT();

    for (int ck = 0; ck < NCH; ck++) {
        const int st = ck % NSTAGE;
        if (ck + 2 < NCH) load_chunk(ck + 2, (ck + 2) % NSTAGE);
        CP_COMMIT();
        CP_WAIT2();
        __syncthreads();

        const uint32_t sA = sb + st * STAGE_BYTES;
        const uint32_t sB = sA + A_BYTES;
#pragma unroll
        for (int k16 = 0; k16 < 4; k16++) {
            const int kc = k16 * 16;
            uint32_t afr[4][4];
#pragma unroll
            for (int mt = 0; mt < 4; mt++) {
                const int row  = wm * 64 + mt * 16 + (lane & 15);
                const int kcol = kc + ((lane & 16) >> 1);
                ldm_x4(afr[mt][0], afr[mt][1], afr[mt][2], afr[mt][3],
                       sA + SWZ(row * 128 + kcol * 2));
            }
            uint32_t bfr[2][4];
#pragma unroll
            for (int p = 0; p < 2; p++) {
                const int row  = wn * 32 + p * 16 + (lane & 7) + ((lane & 16) >> 1);
                const int kcol = kc + ((lane & 8) ? 8 : 0);
                ldm_x4(bfr[p][0], bfr[p][1], bfr[p][2], bfr[p][3],
                       sB + SWZ(row * 128 + kcol * 2));
            }
#pragma unroll
            for (int mt = 0; mt < 4; mt++)
#pragma unroll
                for (int nt = 0; nt < 4; nt++)
                    mma_bf16(acc[mt][nt], afr[mt],
                             bfr[nt >> 1][(nt & 1) * 2],
                             bfr[nt >> 1][(nt & 1) * 2 + 1]);
        }
        __syncthreads();
    }

    // ---- epilogue: pair lanes via shfl_xor(1) so each lane owns a full quad ----
    const int odd = lane & 1;
    const int q   = (lane & 2) >> 1;       // which quad within the 8-col group
#pragma unroll
    for (int mt = 0; mt < 4; mt++) {
#pragma unroll
        for (int nt = 0; nt < 4; nt++) {
            float o0 = __shfl_xor_sync(0xffffffffu, acc[mt][nt][0], 1);
            float o1 = __shfl_xor_sync(0xffffffffu, acc[mt][nt][1], 1);
            float o2 = __shfl_xor_sync(0xffffffffu, acc[mt][nt][2], 1);
            float o3 = __shfl_xor_sync(0xffffffffu, acc[mt][nt][3], 1);
            float gi, gf, gg, go;
            int mrow;
            if (!odd) {
                gi = acc[mt][nt][0]; gf = acc[mt][nt][1];
                gg = o0;             go = o1;
                mrow = m0 + wm * 64 + mt * 16 + (lane >> 2);
            } else {
                gi = o2;             gf = o3;
                gg = acc[mt][nt][2]; go = acc[mt][nt][3];
                mrow = m0 + wm * 64 + mt * 16 + (lane >> 2) + 8;
            }
            const int nb = n0 + wn * 32 + nt * 8 + q * 4;
            const float4 bv = *(const float4*)&bias[nb];
            gi += bv.x; gf += bv.y; gg += bv.z; go += bv.w;
            const int j = nb >> 2;
            const size_t sidx = (size_t)mrow * HID + j;
            float cold = g_c[sidx];
            float cn = fsigmoid(gf) * cold + fsigmoid(gi) * ftanh(gg);
            g_c[sidx] = cn;
            float hn = fsigmoid(go) * ftanh(cn);
            __nv_bfloat16 hb = __float2bfloat16(hn);
            hho[sidx] = hb;
            hlo[sidx] = __float2bfloat16(hn - __bfloat162float(hb));
        }
    }
}

// ---------------- decoder output + next-step input split ----------------
__global__ void out_kernel(int pp, const float* __restrict__ W_out,
                           const float* __restrict__ b_out,
                           float* __restrict__ out) {
    int gw   = (blockIdx.x * blockDim.x + threadIdx.x) >> 5;
    int lane = threadIdx.x & 31;
    if (gw >= BATCH) return;
    const __nv_bfloat16* hh = g_Hh[pp] + (size_t)gw * HID;
    const __nv_bfloat16* hl = g_Hl[pp] + (size_t)gw * HID;
    float s0 = 0.0f, s1 = 0.0f;
#pragma unroll
    for (int k = lane; k < HID; k += 32) {
        float hv = __bfloat162float(hh[k]) + __bfloat162float(hl[k]);
        s0 += hv * W_out[k];
        s1 += hv * W_out[HID + k];
    }
#pragma unroll
    for (int off = 16; off > 0; off >>= 1) {
        s0 += __shfl_down_sync(0xffffffffu, s0, off);
        s1 += __shfl_down_sync(0xffffffffu, s1, off);
    }
    if (lane == 0) {
        float o0 = s0 + b_out[0];
        float o1 = s1 + b_out[1];
        out[gw * 2 + 0] = o0;
        out[gw * 2 + 1] = o1;
        __nv_bfloat16 h0 = __float2bfloat16(o0);
        __nv_bfloat16 h1 = __float2bfloat16(o1);
        g_Xdh[gw * EMB + 0] = h0;
        g_Xdh[gw * EMB + 1] = h1;
        g_Xdl[gw * EMB + 0] = __float2bfloat16(o0 - __bfloat162float(h0));
        g_Xdl[gw * EMB + 1] = __float2bfloat16(o1 - __bfloat162float(h1));
    }
}

// ---------------- launch ----------------
extern "C" void kernel_launch(void* const* d_in, const int* in_sizes, int n_in,
                              void* d_out, int out_size) {
    const float* x        = (const float*)d_in[0];
    const float* W_emb    = (const float*)d_in[1];
    const float* b_emb    = (const float*)d_in[2];
    const float* W_ih_enc = (const float*)d_in[3];
    const float* W_hh_enc = (const float*)d_in[4];
    const float* b_enc    = (const float*)d_in[5];
    const float* W_ih_dec = (const float*)d_in[6];
    const float* W_hh_dec = (const float*)d_in[7];
    const float* b_dec    = (const float*)d_in[8];
    const float* W_out    = (const float*)d_in[9];
    const float* b_out    = (const float*)d_in[10];
    float* out = (float*)d_out;

    cudaFuncSetAttribute(lstm_step_kernel<true>,
                         cudaFuncAttributeMaxDynamicSharedMemorySize, SMEM_DYN_TOTAL);
    cudaFuncSetAttribute(lstm_step_kernel<false>,
                         cudaFuncAttributeMaxDynamicSharedMemorySize, SMEM_DYN_TOTAL);

    pack_kernel<true><<<(NG * KTOT + 255) / 256, 256>>>(W_ih_enc, W_hh_enc, b_enc);
    pack_kernel<false><<<(NG * KTOT + 255) / 256, 256>>>(W_ih_dec, W_hh_dec, b_dec);
    init_state_kernel<<<(BATCH * HID + 255) / 256, 256>>>();
    embed_kernel<<<(SEQ * BATCH * EMB + 255) / 256, 256>>>(x, W_emb, b_emb);
    dec_prep_kernel<<<(BATCH * EMB + 255) / 256, 256>>>(x);

    dim3 grid(BATCH / M_CTA, NG / N_CTA);   // (64, 8)
    int pp = 0;

    for (int t = 0; t < SEQ; t++) {
        lstm_step_kernel<true><<<grid, 512, SMEM_DYN_TOTAL>>>(t, pp);
        pp ^= 1;
    }
    for (int t = 0; t < TLEN; t++) {
        lstm_step_kernel<false><<<grid, 512, SMEM_DYN_TOTAL>>>(0, pp);
        pp ^= 1;
        out_kernel<<<(BATCH * 32) / 256, 256>>>(pp, W_out, b_out,
                                                out + (size_t)t * BATCH * INP);
    }
}